// round 1
// baseline (speedup 1.0000x reference)
#include <cuda_runtime.h>
#include <math.h>

// ---------------- scratch (static device globals; no allocation) ----------------
__device__ float g_adp[1024 * 1024];              //   4 MB
__device__ float g_Mstack[1024 * 6144];           //  24 MB  [v, slot*1024+w]
__device__ float g_Xr[24576 * 1024];              // 100 MB  rows=(n,l,c), cols=v
__device__ float g_Z[150994944];                  // 604 MB  [24576, 6144]

// ---------------- adaptive adjacency: softmax(relu(nv1 @ nv2), axis=1) ----------
__global__ void adp_kernel(const float* __restrict__ nv1, const float* __restrict__ nv2) {
    int v = blockIdx.x;
    int tid = threadIdx.x;
    __shared__ float e1[10];
    __shared__ float red[256];
    if (tid < 10) e1[tid] = nv1[v * 10 + tid];
    __syncthreads();

    float vals[4];
#pragma unroll
    for (int q = 0; q < 4; q++) {
        int w = tid + q * 256;
        float s = 0.f;
#pragma unroll
        for (int t = 0; t < 10; t++) s += e1[t] * nv2[t * 1024 + w];
        vals[q] = fmaxf(s, 0.f);
    }
    // block max
    float m = fmaxf(fmaxf(vals[0], vals[1]), fmaxf(vals[2], vals[3]));
    red[tid] = m;
    __syncthreads();
    for (int s = 128; s > 0; s >>= 1) {
        if (tid < s) red[tid] = fmaxf(red[tid], red[tid + s]);
        __syncthreads();
    }
    m = red[0];
    __syncthreads();

    float e[4];
    float ssum = 0.f;
#pragma unroll
    for (int q = 0; q < 4; q++) { e[q] = expf(vals[q] - m); ssum += e[q]; }
    red[tid] = ssum;
    __syncthreads();
    for (int s = 128; s > 0; s >>= 1) {
        if (tid < s) red[tid] += red[tid + s];
        __syncthreads();
    }
    float denom = red[0];
#pragma unroll
    for (int q = 0; q < 4; q++) {
        int w = tid + q * 256;
        g_adp[v * 1024 + w] = e[q] / denom;
    }
}

// ---------------- copy A1, A2, adp into Mstack slots 0, 2, 4 --------------------
__global__ void copy_slots(const float* __restrict__ A1, const float* __restrict__ A2) {
    int g = blockIdx.x * 256 + threadIdx.x;       // 3 * 2^20 total
    int which = g >> 20;
    int rem = g & 0xFFFFF;
    int v = rem >> 10, w = rem & 1023;
    float val = (which == 0) ? A1[rem] : (which == 1) ? A2[rem] : g_adp[rem];
    int slot = which * 2;                          // 0, 2, 4
    g_Mstack[v * 6144 + slot * 1024 + w] = val;
}

// ---------------- generic 128x128x16 SGEMM body (8x8 per thread) ----------------
__device__ __forceinline__ void sgemm_body(
    const float* __restrict__ A, const float* __restrict__ B, float* __restrict__ C,
    int K, int lda, int ldb, int ldc)
{
    __shared__ float As[2][16][132];   // transposed, padded
    __shared__ float Bs[2][16][128];

    const int tid = threadIdx.x;
    const int bm = blockIdx.y * 128;
    const int bn = blockIdx.x * 128;
    const int tx = tid & 15;
    const int ty = tid >> 4;
    const int a_row = tid >> 2;             // 0..63
    const int a_col = (tid & 3) << 2;       // 0,4,8,12
    const int b_row = tid >> 5;             // 0..7
    const int b_col = (tid & 31) << 2;      // 0..124

    const float* Aptr = A + (size_t)bm * lda;
    const float* Bptr = B + bn;

    float acc[8][8];
#pragma unroll
    for (int i = 0; i < 8; i++)
#pragma unroll
        for (int j = 0; j < 8; j++) acc[i][j] = 0.f;

    // prologue: tile 0
    {
        float4 a0 = *(const float4*)(Aptr + (size_t)a_row * lda + a_col);
        float4 a1 = *(const float4*)(Aptr + (size_t)(a_row + 64) * lda + a_col);
        float4 b0 = *(const float4*)(Bptr + (size_t)b_row * ldb + b_col);
        float4 b1 = *(const float4*)(Bptr + (size_t)(b_row + 8) * ldb + b_col);
        As[0][a_col + 0][a_row] = a0.x; As[0][a_col + 1][a_row] = a0.y;
        As[0][a_col + 2][a_row] = a0.z; As[0][a_col + 3][a_row] = a0.w;
        As[0][a_col + 0][a_row + 64] = a1.x; As[0][a_col + 1][a_row + 64] = a1.y;
        As[0][a_col + 2][a_row + 64] = a1.z; As[0][a_col + 3][a_row + 64] = a1.w;
        *(float4*)&Bs[0][b_row][b_col] = b0;
        *(float4*)&Bs[0][b_row + 8][b_col] = b1;
    }
    __syncthreads();

    const int nt = K >> 4;
    for (int t = 0; t < nt; t++) {
        const int cur = t & 1;
        float4 a0, a1, b0, b1;
        if (t + 1 < nt) {
            int k0 = (t + 1) << 4;
            a0 = *(const float4*)(Aptr + (size_t)a_row * lda + k0 + a_col);
            a1 = *(const float4*)(Aptr + (size_t)(a_row + 64) * lda + k0 + a_col);
            b0 = *(const float4*)(Bptr + (size_t)(k0 + b_row) * ldb + b_col);
            b1 = *(const float4*)(Bptr + (size_t)(k0 + b_row + 8) * ldb + b_col);
        }
#pragma unroll
        for (int kk = 0; kk < 16; kk++) {
            float af[8], bf[8];
            *(float4*)(af)     = *(const float4*)&As[cur][kk][ty * 8];
            *(float4*)(af + 4) = *(const float4*)&As[cur][kk][ty * 8 + 4];
            *(float4*)(bf)     = *(const float4*)&Bs[cur][kk][tx * 8];
            *(float4*)(bf + 4) = *(const float4*)&Bs[cur][kk][tx * 8 + 4];
#pragma unroll
            for (int i = 0; i < 8; i++)
#pragma unroll
                for (int j = 0; j < 8; j++)
                    acc[i][j] = fmaf(af[i], bf[j], acc[i][j]);
        }
        if (t + 1 < nt) {
            const int nxt = cur ^ 1;
            As[nxt][a_col + 0][a_row] = a0.x; As[nxt][a_col + 1][a_row] = a0.y;
            As[nxt][a_col + 2][a_row] = a0.z; As[nxt][a_col + 3][a_row] = a0.w;
            As[nxt][a_col + 0][a_row + 64] = a1.x; As[nxt][a_col + 1][a_row + 64] = a1.y;
            As[nxt][a_col + 2][a_row + 64] = a1.z; As[nxt][a_col + 3][a_row + 64] = a1.w;
            *(float4*)&Bs[nxt][b_row][b_col] = b0;
            *(float4*)&Bs[nxt][b_row + 8][b_col] = b1;
        }
        __syncthreads();
    }

    float* Cp = C + (size_t)(bm + ty * 8) * ldc + bn + tx * 8;
#pragma unroll
    for (int i = 0; i < 8; i++) {
        *(float4*)(Cp + (size_t)i * ldc)     = make_float4(acc[i][0], acc[i][1], acc[i][2], acc[i][3]);
        *(float4*)(Cp + (size_t)i * ldc + 4) = make_float4(acc[i][4], acc[i][5], acc[i][6], acc[i][7]);
    }
}

// squares: A1^2 -> slot1, A2^2 -> slot3, adp^2 -> slot5 (batched on blockIdx.z)
__global__ __launch_bounds__(256, 2) void squares_kernel(const float* __restrict__ A1,
                                                         const float* __restrict__ A2) {
    const float* src = (blockIdx.z == 0) ? A1 : (blockIdx.z == 1) ? A2 : g_adp;
    int slot = blockIdx.z * 2 + 1;                // 1, 3, 5
    sgemm_body(src, src, g_Mstack + slot * 1024, 1024, 1024, 1024, 6144);
}

// main GEMM: Z[24576,6144] = Xr[24576,1024] @ Mstack[1024,6144]
__global__ __launch_bounds__(256, 2) void main_gemm_kernel() {
    sgemm_body(g_Xr, g_Mstack, g_Z, 1024, 1024, 6144, 6144);
}

// ---------------- transpose x [n,c,v,l] -> Xr rows=(n,l,c), cols=v --------------
__global__ void transpose_x(const float* __restrict__ x) {
    __shared__ float s[256 * 13];
    int n = blockIdx.z, c = blockIdx.y, v0 = blockIdx.x * 256;
    int tid = threadIdx.x;
    const float* src = x + ((size_t)(n * 32 + c) * 1024 + v0) * 12;
    for (int i = tid; i < 3072; i += 256) {
        int v = i / 12, l = i - v * 12;
        s[v * 13 + l] = src[i];
    }
    __syncthreads();
#pragma unroll
    for (int l = 0; l < 12; l++) {
        g_Xr[(size_t)((n * 12 + l) * 32 + c) * 1024 + v0 + tid] = s[tid * 13 + l];
    }
}

// ---------------- epilogue: 1x1 conv over 7 blocks, fused from Xr + Z -----------
// grid: (8 wtiles * 12 l, 64 n), 256 threads. Thread owns 4 o's x 4 w's.
__global__ __launch_bounds__(256) void epilogue_kernel(
    const float* __restrict__ W, const float* __restrict__ bias, float* __restrict__ out)
{
    __shared__ float Hs[32][128];
    __shared__ float Ws[32 * 32];
    int l = blockIdx.x % 12;
    int wt = blockIdx.x / 12;
    int n = blockIdx.y;
    int w0 = wt * 128;
    int tid = threadIdx.x;
    int og = tid >> 5;          // 0..7  -> o = og*4 + j
    int wl = tid & 31;          // w = w0 + wl + 32*i

    int rbase = (n * 12 + l) * 32;

    float acc[4][4];
#pragma unroll
    for (int j = 0; j < 4; j++) {
        float bj = bias[og * 4 + j];
#pragma unroll
        for (int i = 0; i < 4; i++) acc[j][i] = bj;
    }

    for (int k = 0; k < 7; k++) {
        // load H chunk [32 c, 128 w]
        if (k == 0) {
            for (int i = tid; i < 4096; i += 256) {
                int c = i >> 7, w = i & 127;
                Hs[c][w] = g_Xr[(size_t)(rbase + c) * 1024 + w0 + w];
            }
        } else {
            for (int i = tid; i < 4096; i += 256) {
                int c = i >> 7, w = i & 127;
                Hs[c][w] = g_Z[(size_t)(rbase + c) * 6144 + (k - 1) * 1024 + w0 + w];
            }
        }
        // load W block [32 o, 32 c]
        for (int i = tid; i < 1024; i += 256)
            Ws[i] = W[(i >> 5) * 224 + 32 * k + (i & 31)];
        __syncthreads();

#pragma unroll 4
        for (int c = 0; c < 32; c++) {
            float wv[4], hv[4];
#pragma unroll
            for (int j = 0; j < 4; j++) wv[j] = Ws[(og * 4 + j) * 32 + c];
#pragma unroll
            for (int i = 0; i < 4; i++) hv[i] = Hs[c][wl + 32 * i];
#pragma unroll
            for (int j = 0; j < 4; j++)
#pragma unroll
                for (int i = 0; i < 4; i++)
                    acc[j][i] = fmaf(wv[j], hv[i], acc[j][i]);
        }
        __syncthreads();
    }

#pragma unroll
    for (int j = 0; j < 4; j++) {
        int o = og * 4 + j;
#pragma unroll
        for (int i = 0; i < 4; i++) {
            int w = w0 + wl + 32 * i;
            out[((size_t)(n * 32 + o) * 1024 + w) * 12 + l] = acc[j][i];
        }
    }
}

// -------------------------------- launch ----------------------------------------
extern "C" void kernel_launch(void* const* d_in, const int* in_sizes, int n_in,
                              void* d_out, int out_size) {
    const float* x   = (const float*)d_in[0];
    const float* A1  = (const float*)d_in[1];
    const float* A2  = (const float*)d_in[2];
    const float* nv1 = (const float*)d_in[3];
    const float* nv2 = (const float*)d_in[4];
    const float* W   = (const float*)d_in[5];
    const float* b   = (const float*)d_in[6];
    float* out = (float*)d_out;

    adp_kernel<<<1024, 256>>>(nv1, nv2);
    copy_slots<<<(3 * 1024 * 1024) / 256, 256>>>(A1, A2);
    {
        dim3 g(8, 8, 3);
        squares_kernel<<<g, 256>>>(A1, A2);
    }
    transpose_x<<<dim3(4, 32, 64), 256>>>(x);
    main_gemm_kernel<<<dim3(48, 192), 256>>>();
    epilogue_kernel<<<dim3(96, 64), 256>>>(W, b, out);
}